// round 5
// baseline (speedup 1.0000x reference)
#include <cuda_runtime.h>

#define POOLK 7
#define NBINS (POOLK * POOLK)
#define NUM_ROIS 300
#define FH 50
#define FW 50
#define FC 512

// Scratch (no cudaMalloc allowed)
__device__ float g_fmax[FH * FW];
__device__ float g_binmax[NUM_ROIS * NBINS];

// K1: one warp per pixel, max over 512 contiguous channels (5 MB DRAM read).
__global__ void fmax_kernel(const float* __restrict__ fm) {
    int warp = (blockIdx.x * blockDim.x + threadIdx.x) >> 5;
    int lane = threadIdx.x & 31;
    if (warp >= FH * FW) return;
    const float4* p = reinterpret_cast<const float4*>(fm + (size_t)warp * FC);
    float m = -INFINITY;
#pragma unroll
    for (int k = 0; k < 4; k++) {
        float4 v = p[lane + 32 * k];
        m = fmaxf(m, fmaxf(fmaxf(v.x, v.y), fmaxf(v.z, v.w)));
    }
#pragma unroll
    for (int off = 16; off > 0; off >>= 1)
        m = fmaxf(m, __shfl_xor_sync(0xffffffffu, m, off));
    if (lane == 0) g_fmax[warp] = m;
}

// K2: one THREAD per (roi, bin). Serial bin-max with independent loads (MLP),
// no shuffles. 14700 threads total.
__global__ void binmax_kernel(const float* __restrict__ rois) {
    int idx = blockIdx.x * blockDim.x + threadIdx.x;
    if (idx >= NUM_ROIS * NBINS) return;

    int r = idx / NBINS;
    int bin = idx - r * NBINS;
    int i = bin / POOLK;
    int j = bin - i * POOLK;

    const float* roi = rois + r * 5;
    // reference: (rois * (1/16)).astype(int32) -> truncation; inputs >= 0
    int x1 = (int)(__ldg(roi + 1) * 0.0625f);
    int y1 = (int)(__ldg(roi + 2) * 0.0625f);
    int x2 = (int)(__ldg(roi + 3) * 0.0625f);
    int y2 = (int)(__ldg(roi + 4) * 0.0625f);
    int rh = y2 - y1 + 1;
    int rw = x2 - x1 + 1;

    int hs = min(max(y1 + (i * rh) / POOLK, 0), FH);
    int he = min(max(y1 + ((i + 1) * rh + POOLK - 1) / POOLK, 0), FH);
    int ws = min(max(x1 + (j * rw) / POOLK, 0), FW);
    int we = min(max(x1 + ((j + 1) * rw + POOLK - 1) / POOLK, 0), FW);

    float m = -INFINITY;
    for (int y = hs; y < he; y++) {
        const float* row = g_fmax + y * FW;
#pragma unroll 4
        for (int x = ws; x < we; x++)
            m = fmaxf(m, __ldg(row + x));
    }
    g_binmax[idx] = m;
}

// K3: pure broadcast write — one uniform load + one STG.128 per thread.
// Thread t writes floats [4t, 4t+4) of out; bin index = t >> 7.
__global__ void write_kernel(float* __restrict__ out) {
    int t = blockIdx.x * blockDim.x + threadIdx.x;
    float v = g_binmax[t >> 7];
    reinterpret_cast<float4*>(out)[t] = make_float4(v, v, v, v);
}

extern "C" void kernel_launch(void* const* d_in, const int* in_sizes, int n_in,
                              void* d_out, int out_size) {
    const float* rois = (const float*)d_in[0];          // (300, 5)
    const float* feature_maps = (const float*)d_in[1];  // (50, 50, 512)
    float* out = (float*)d_out;                         // (300, 7, 7, 512)

    // K1: 2500 warps; 128-thread blocks -> 625 blocks (cover all SMs)
    fmax_kernel<<<(FH * FW * 32 + 127) / 128, 128>>>(feature_maps);

    // K2: 14700 threads
    binmax_kernel<<<(NUM_ROIS * NBINS + 255) / 256, 256>>>(rois);

    // K3: 300*49*512 floats = 7,526,400 -> 1,881,600 float4 threads
    // = exactly 7350 blocks of 256.
    write_kernel<<<(NUM_ROIS * NBINS * (FC / 4)) / 256, 256>>>(out);
}